// round 10
// baseline (speedup 1.0000x reference)
#include <cuda_runtime.h>
#include <cuda_fp16.h>
#include <cstdint>
#include <math.h>

#define B_  2048
#define H_  4
#define D_  4096
#define M_  8
#define DM_ 512

// ---------------- scratch (fp16 operands) ----------------
__device__ __align__(16) __half g_Yh[(size_t)B_ * D_];
__device__ __align__(16) __half g_Wh[(size_t)D_ * D_];

// ---------------- helpers ----------------
__device__ __forceinline__ uint32_t smem_u32(const void* p) {
    uint32_t a;
    asm("{ .reg .u64 t; cvta.to.shared.u64 t, %1; cvt.u32.u64 %0, t; }" : "=r"(a) : "l"(p));
    return a;
}

#define CP_ASYNC16(dst, src) \
    asm volatile("cp.async.cg.shared.global [%0], [%1], 16;" :: "r"(dst), "l"(src))
#define CP_COMMIT()  asm volatile("cp.async.commit_group;" ::: "memory")
#define CP_WAIT1()   asm volatile("cp.async.wait_group 1;" ::: "memory")

#define LDSM_X4(r, addr) \
    asm volatile("ldmatrix.sync.aligned.m8n8.x4.shared.b16 {%0,%1,%2,%3}, [%4];" \
                 : "=r"((r)[0]), "=r"((r)[1]), "=r"((r)[2]), "=r"((r)[3]) : "r"(addr))

__device__ __forceinline__ void mma_f16(float* d, const uint32_t* a, const uint32_t* b) {
    asm volatile(
        "mma.sync.aligned.m16n8k16.row.col.f32.f16.f16.f32 "
        "{%0,%1,%2,%3}, {%4,%5,%6,%7}, {%8,%9}, {%0,%1,%2,%3};"
        : "+f"(d[0]), "+f"(d[1]), "+f"(d[2]), "+f"(d[3])
        : "r"(a[0]), "r"(a[1]), "r"(a[2]), "r"(a[3]), "r"(b[0]), "r"(b[1]));
}

__device__ __forceinline__ float sigmoidf_(float v) {
    return __fdividef(1.0f, 1.0f + __expf(-v));
}

// ---------------- kernel 1: fused prologue ----------------
#define WBLK ((int)(((long long)D_ * D_ / 8) / 256))   // 8192 blocks
#define YBLK ((int)(((long long)B_ * D_ / 8) / 256))   // 4096 blocks

__global__ __launch_bounds__(256)
void prologue_kernel(const float* __restrict__ W,
                     const float* __restrict__ x,
                     const float* __restrict__ lW,
                     const float* __restrict__ lb) {
    const int bid = blockIdx.x;
    if (bid < WBLK) {
        long long base = ((long long)bid * 256 + threadIdx.x) * 8;
        float4 v0 = *(const float4*)(W + base);
        float4 v1 = *(const float4*)(W + base + 4);
        __half2 h[4];
        h[0] = __floats2half2_rn(v0.x, v0.y);
        h[1] = __floats2half2_rn(v0.z, v0.w);
        h[2] = __floats2half2_rn(v1.x, v1.y);
        h[3] = __floats2half2_rn(v1.z, v1.w);
        *(uint4*)(g_Wh + base) = *(uint4*)h;
    } else {
        long long flat = ((long long)(bid - WBLK) * 256 + threadIdx.x) * 8;
        int c = (int)(flat % DM_);
        long long t = flat / DM_;
        int b = (int)(t % B_);
        int m = (int)(t / B_);

        float w0 = lW[m * H_ + 0], w1 = lW[m * H_ + 1];
        float w2 = lW[m * H_ + 2], w3 = lW[m * H_ + 3];
        float bb = lb[m];

        const float* xb = x + (long long)b * H_ * D_ + m * DM_ + c;
        __half2 hv[4];
#pragma unroll
        for (int q = 0; q < 2; q++) {
            float4 v0 = *(const float4*)(xb + 0ll * D_ + q * 4);
            float4 v1 = *(const float4*)(xb + 1ll * D_ + q * 4);
            float4 v2 = *(const float4*)(xb + 2ll * D_ + q * 4);
            float4 v3 = *(const float4*)(xb + 3ll * D_ + q * 4);
            float rx = fmaf(w0, v0.x, fmaf(w1, v1.x, fmaf(w2, v2.x, fmaf(w3, v3.x, bb))));
            float ry = fmaf(w0, v0.y, fmaf(w1, v1.y, fmaf(w2, v2.y, fmaf(w3, v3.y, bb))));
            float rz = fmaf(w0, v0.z, fmaf(w1, v1.z, fmaf(w2, v2.z, fmaf(w3, v3.z, bb))));
            float rw = fmaf(w0, v0.w, fmaf(w1, v1.w, fmaf(w2, v2.w, fmaf(w3, v3.w, bb))));
            hv[q * 2 + 0] = __floats2half2_rn(rx, ry);
            hv[q * 2 + 1] = __floats2half2_rn(rz, rw);
        }
        *(uint4*)(g_Yh + flat) = *(uint4*)hv;
    }
}

// ---------------- kernel 2: fp16 mma GEMM, 64x64 CTA tiles ----------------
// 2048 CTAs of 64 threads (2 warps, 32x64 warp tile) -> per-SM tile count
// ~13.8 so the wave-quantization tail shrinks from ~15% to ~1%.
#define TT      64                  // CTA tile (square)
#define KC      64                  // halves per chunk (128 B rows)
#define NCHUNK  (D_ / KC)           // 64
#define SROW    72                  // padded row stride in halves (144 B)
#define STAGE_H (2 * TT * SROW)     // halves per stage, A then B (9216)
#define NSTAGE  3
#define SM_BYTES (NSTAGE * STAGE_H * 2)   // 55296 B
#define NTHR    64

__global__ __launch_bounds__(NTHR, 4)
void gemm_mma_kernel(const float* __restrict__ bias,
                     float* __restrict__ out) {
    extern __shared__ __half sm[];
    const uint32_t smb = smem_u32(sm);

    const int tid  = threadIdx.x;
    const int wm   = tid >> 5;     // warp 0 -> rows 0-31, warp 1 -> rows 32-63
    const int lane = tid & 31;

    const int row0 = blockIdx.y * TT;
    const int col0 = blockIdx.x * TT;

    const __half* Ag = g_Yh + (long long)row0 * D_;
    const __half* Bg = g_Wh + (long long)col0 * D_;

    uint32_t stage_base[NSTAGE];
#pragma unroll
    for (int s = 0; s < NSTAGE; s++) stage_base[s] = smb + (uint32_t)(s * STAGE_H) * 2;

    // ldmatrix offsets (halves; k added per step)
    int a_off[2], b_off[4];
#pragma unroll
    for (int am = 0; am < 2; am++)
        a_off[am] = (wm * 32 + am * 16 + (lane & 15)) * SROW + ((lane >> 4) << 3);
    {
        const int seg = lane >> 3;
#pragma unroll
        for (int bn = 0; bn < 4; bn++)
            b_off[bn] = (TT + bn * 16 + ((seg >> 1) << 3) + (lane & 7)) * SROW
                      + ((seg & 1) << 3);
    }

    // gmem->smem: (64 A + 64 B) rows x 8 16B-chunks / 64 threads = 16 each
    const int lrow = tid >> 3;     // 0..7, +8 per i
    const int lc8  = tid & 7;

    float d[2][8][4];
#pragma unroll
    for (int i = 0; i < 2; i++)
#pragma unroll
        for (int j = 0; j < 8; j++)
#pragma unroll
            for (int q = 0; q < 4; q++) d[i][j][q] = 0.0f;

    auto load_chunk = [&](int it, int s) {
        const int k0 = it * KC;
        const uint32_t aS = stage_base[s];
        const uint32_t bS = stage_base[s] + (uint32_t)(TT * SROW) * 2;
#pragma unroll
        for (int i = 0; i < 8; i++) {
            const int r = lrow + i * 8;
            CP_ASYNC16(aS + (uint32_t)(r * SROW + lc8 * 8) * 2,
                       Ag + (long long)r * D_ + k0 + lc8 * 8);
        }
#pragma unroll
        for (int i = 0; i < 8; i++) {
            const int r = lrow + i * 8;
            CP_ASYNC16(bS + (uint32_t)(r * SROW + lc8 * 8) * 2,
                       Bg + (long long)r * D_ + k0 + lc8 * 8);
        }
    };

    load_chunk(0, 0);
    CP_COMMIT();
    load_chunk(1, 1);
    CP_COMMIT();

    uint32_t a[2][2][4], b[2][4][4];

    int s = 0;
    for (int it = 0; it < NCHUNK; ++it) {
        CP_WAIT1();            // chunk `it` resident
        __syncthreads();

        if (it + 2 < NCHUNK) {
            int s2 = s + 2; if (s2 >= NSTAGE) s2 -= NSTAGE;
            load_chunk(it + 2, s2);
        }
        CP_COMMIT();

        const uint32_t base = stage_base[s];

        // fragment prologue: kk=0 into buffer 0
#pragma unroll
        for (int am = 0; am < 2; am++)
            LDSM_X4(a[0][am], base + (uint32_t)a_off[am] * 2);
#pragma unroll
        for (int bn = 0; bn < 4; bn++)
            LDSM_X4(b[0][bn], base + (uint32_t)b_off[bn] * 2);

#pragma unroll
        for (int kk4 = 0; kk4 < 4; kk4++) {
            const int cur = kk4 & 1;
            if (kk4 < 3) {       // prefetch next kk fragments into alt buffer
                const int kn = (kk4 + 1) * 16;
#pragma unroll
                for (int am = 0; am < 2; am++)
                    LDSM_X4(a[cur ^ 1][am], base + (uint32_t)(a_off[am] + kn) * 2);
#pragma unroll
                for (int bn = 0; bn < 4; bn++)
                    LDSM_X4(b[cur ^ 1][bn], base + (uint32_t)(b_off[bn] + kn) * 2);
            }
#pragma unroll
            for (int am = 0; am < 2; am++)
#pragma unroll
                for (int j = 0; j < 8; j++)
                    mma_f16(d[am][j], a[cur][am], &b[cur][j >> 1][(j & 1) * 2]);
        }
        if (++s >= NSTAGE) s = 0;
    }

    // epilogue: bias + sigmoid
    const int g = lane >> 2, t4 = lane & 3;
#pragma unroll
    for (int am = 0; am < 2; am++) {
        const int r0 = row0 + wm * 32 + am * 16 + g;
#pragma unroll
        for (int j = 0; j < 8; j++) {
            const int c = col0 + j * 8 + t4 * 2;
            const float bx = bias[c], by = bias[c + 1];
            float2 o0, o1;
            o0.x = sigmoidf_(d[am][j][0] + bx);
            o0.y = sigmoidf_(d[am][j][1] + by);
            o1.x = sigmoidf_(d[am][j][2] + bx);
            o1.y = sigmoidf_(d[am][j][3] + by);
            *(float2*)(out + (long long)r0 * D_ + c)       = o0;
            *(float2*)(out + (long long)(r0 + 8) * D_ + c) = o1;
        }
    }
}

// ---------------- launch ----------------
extern "C" void kernel_launch(void* const* d_in, const int* in_sizes, int n_in,
                              void* d_out, int out_size) {
    const float* x  = (const float*)d_in[0];
    const float* lW = (const float*)d_in[1];
    const float* lb = (const float*)d_in[2];
    const float* pW = (const float*)d_in[3];
    const float* pb = (const float*)d_in[4];
    float* out = (float*)d_out;

    prologue_kernel<<<WBLK + YBLK, 256>>>(pW, x, lW, lb);

    cudaFuncSetAttribute(gemm_mma_kernel,
                         cudaFuncAttributeMaxDynamicSharedMemorySize, SM_BYTES);
    dim3 grid(D_ / TT, B_ / TT);   // (64, 32) = 2048 CTAs
    gemm_mma_kernel<<<grid, NTHR, SM_BYTES>>>(pb, out);
}